// round 1
// baseline (speedup 1.0000x reference)
#include <cuda_runtime.h>
#include <math.h>

// ---------------------------------------------------------------------------
// ProbAttention (Informer ProbSparse) — fp32 baseline
// Shapes: B=16, L=2048, D_IN=512, HID=512, H=8, D=64, U=40
// All reference reshapes are flat-contiguous views; we keep flat layouts.
// ---------------------------------------------------------------------------

#define B_    16
#define L_    2048
#define DIN_  512
#define HID_  512
#define H_    8
#define D_    64
#define U_    40
#define BH_   (B_ * H_)      // 128
#define MROWS (B_ * L_)      // 32768

#define NEG_INF (__int_as_float(0xff800000))

// Scratch (no cudaMalloc allowed): ~268 MB of device globals.
__device__ float g_q[(size_t)MROWS * HID_];
__device__ float g_k[(size_t)MROWS * HID_];
__device__ float g_v[(size_t)MROWS * HID_];
__device__ float g_ctx[(size_t)MROWS * HID_];
__device__ float g_dot[BH_ * L_];
__device__ int   g_mtop[BH_ * U_];

// ---------------------------------------------------------------------------
// Kernel 1: QKV projection GEMMs.  C = A(32768x512) @ W(512x512), z in {q,k,v}
// 128x128 block tile, BK=8, 256 threads, 8x8 microtile.
// ---------------------------------------------------------------------------
__global__ __launch_bounds__(256) void sgemm_qkv(
    const float* __restrict__ Aq, const float* __restrict__ Ak, const float* __restrict__ Av,
    const float* __restrict__ Wq, const float* __restrict__ Wk, const float* __restrict__ Wv)
{
    const float* A; const float* W; float* C;
    if (blockIdx.z == 0)      { A = Aq; W = Wq; C = g_q; }
    else if (blockIdx.z == 1) { A = Ak; W = Wk; C = g_k; }
    else                      { A = Av; W = Wv; C = g_v; }

    __shared__ float As[8][128];   // transposed A tile
    __shared__ float Bs[8][128];

    const int t  = threadIdx.x;
    const int tx = t & 15;         // N direction (x8)
    const int ty = t >> 4;         // M direction (x8)

    const int arow = t >> 1;          // 0..127
    const int akk  = (t & 1) * 4;     // 0 or 4
    const int brow = t >> 5;          // 0..7
    const int bcol = (t & 31) * 4;    // 0..124

    const size_t m0 = (size_t)blockIdx.y * 128;
    const int    n0 = blockIdx.x * 128;

    const float* Ap = A + (m0 + arow) * DIN_ + akk;
    const float* Wp = W + (size_t)brow * HID_ + n0 + bcol;

    float acc[8][8];
#pragma unroll
    for (int i = 0; i < 8; i++)
#pragma unroll
        for (int j = 0; j < 8; j++) acc[i][j] = 0.f;

    for (int kb = 0; kb < DIN_; kb += 8) {
        float4 av = *(const float4*)(Ap + kb);
        float4 bv = *(const float4*)(Wp + (size_t)kb * HID_);
        __syncthreads();
        As[akk + 0][arow] = av.x;
        As[akk + 1][arow] = av.y;
        As[akk + 2][arow] = av.z;
        As[akk + 3][arow] = av.w;
        *(float4*)&Bs[brow][bcol] = bv;
        __syncthreads();
#pragma unroll
        for (int k = 0; k < 8; k++) {
            float a[8], b[8];
            *(float4*)&a[0] = *(const float4*)&As[k][ty * 8];
            *(float4*)&a[4] = *(const float4*)&As[k][ty * 8 + 4];
            *(float4*)&b[0] = *(const float4*)&Bs[k][tx * 8];
            *(float4*)&b[4] = *(const float4*)&Bs[k][tx * 8 + 4];
#pragma unroll
            for (int i = 0; i < 8; i++)
#pragma unroll
                for (int j = 0; j < 8; j++)
                    acc[i][j] = fmaf(a[i], b[j], acc[i][j]);
        }
    }

#pragma unroll
    for (int i = 0; i < 8; i++) {
        float* crow = C + (m0 + ty * 8 + i) * HID_ + n0 + tx * 8;
        float4 o0 = make_float4(acc[i][0], acc[i][1], acc[i][2], acc[i][3]);
        float4 o1 = make_float4(acc[i][4], acc[i][5], acc[i][6], acc[i][7]);
        *(float4*)crow       = o0;
        *(float4*)(crow + 4) = o1;
    }
}

// ---------------------------------------------------------------------------
// Kernel 2: dot[bh,l] = q[bh,l,:] . k[bh,idx[l],:]   (one warp per (bh,l))
// ---------------------------------------------------------------------------
__global__ __launch_bounds__(256) void dot_kernel(const int* __restrict__ idx)
{
    const int gid  = blockIdx.x * blockDim.x + threadIdx.x;
    const int warp = gid >> 5;
    const int lane = gid & 31;
    const int l  = warp & (L_ - 1);
    const int bh = warp >> 11;     // L_=2048 -> shift 11

    const float* qrow = g_q + ((size_t)bh * L_ + l) * D_;
    const float* krow = g_k + ((size_t)bh * L_ + idx[l]) * D_;
    float s = qrow[lane] * krow[lane] + qrow[lane + 32] * krow[lane + 32];
#pragma unroll
    for (int o = 16; o > 0; o >>= 1) s += __shfl_xor_sync(0xffffffffu, s, o);
    if (lane == 0) g_dot[warp] = s;
}

// ---------------------------------------------------------------------------
// Kernel 3: top-U indices of dot[bh,:] (monotonic scale => same set as ref's M)
// One block per bh; U iterative argmax passes with tie -> smaller index.
// ---------------------------------------------------------------------------
__global__ __launch_bounds__(256) void topk_kernel()
{
    const int bh = blockIdx.x;
    const int t  = threadIdx.x;
    __shared__ float sv[L_];
    __shared__ float rv[256];
    __shared__ int   ri[256];

    for (int i = t; i < L_; i += 256) sv[i] = g_dot[bh * L_ + i];
    __syncthreads();

    for (int p = 0; p < U_; p++) {
        float bvv = NEG_INF;
        int   bii = 0x7fffffff;
        for (int i = t; i < L_; i += 256) {
            float v = sv[i];
            if (v > bvv || (v == bvv && i < bii)) { bvv = v; bii = i; }
        }
        rv[t] = bvv; ri[t] = bii;
        __syncthreads();
        for (int s = 128; s > 0; s >>= 1) {
            if (t < s) {
                if (rv[t + s] > rv[t] || (rv[t + s] == rv[t] && ri[t + s] < ri[t])) {
                    rv[t] = rv[t + s]; ri[t] = ri[t + s];
                }
            }
            __syncthreads();
        }
        if (t == 0) {
            g_mtop[bh * U_ + p] = ri[0];
            sv[ri[0]] = NEG_INF;
        }
        __syncthreads();
    }
}

// ---------------------------------------------------------------------------
// Kernel 4: context = cumsum(v, axis=L).  One block per bh, thread = d lane.
// ---------------------------------------------------------------------------
__global__ __launch_bounds__(64) void cumsum_kernel()
{
    const int bh = blockIdx.x;
    const int d  = threadIdx.x;
    const float* vp = g_v   + (size_t)bh * L_ * D_ + d;
    float*       cp = g_ctx + (size_t)bh * L_ * D_ + d;
    float acc = 0.f;
#pragma unroll 8
    for (int l = 0; l < L_; l++) {
        acc += vp[(size_t)l * D_];
        cp[(size_t)l * D_] = acc;
    }
}

// ---------------------------------------------------------------------------
// Kernel 5: flash-style attention for the U=40 selected queries per (bh),
// causal mask l > m_top[u], online softmax; scatter result into g_ctx rows.
// One block (256 threads = 8 warps) per bh. Warp w owns u in {w, w+8, ..., w+32}.
// ---------------------------------------------------------------------------
__global__ __launch_bounds__(256) void attn_kernel()
{
    const int bh   = blockIdx.x;
    const int t    = threadIdx.x;
    const int lane = t & 31;
    const int w    = t >> 5;

    __shared__ float qs[U_][D_];      // selected queries
    __shared__ float kst[D_][32];     // k tile, transposed [d][l]
    __shared__ float vs[32][D_];      // v tile [l][d]
    __shared__ float ss[U_][32];      // scores / probs
    __shared__ float accs[U_][D_];    // output accumulators
    __shared__ float mrow[U_], srow[U_], crow[U_];
    __shared__ int   mt[U_];

    if (t < U_) {
        mt[t]   = g_mtop[bh * U_ + t];
        mrow[t] = NEG_INF;
        srow[t] = 0.f;
    }
    __syncthreads();

    for (int i = t; i < U_ * D_; i += 256) {
        int u = i >> 6, d = i & 63;
        qs[u][d]   = g_q[((size_t)bh * L_ + mt[u]) * D_ + d];
        accs[u][d] = 0.f;
    }

    const float* kbase = g_k + (size_t)bh * L_ * D_;
    const float* vbase = g_v + (size_t)bh * L_ * D_;

    for (int tile = 0; tile < L_ / 32; tile++) {
        const int l0 = tile * 32;
        __syncthreads();   // prev PV done reading vs/ss; qs/accs init done on tile 0
        // load k (transposed) + v tiles: 32 rows x 64 cols, float4 per thread x2
#pragma unroll
        for (int i = 0; i < 2; i++) {
            int f   = t + 256 * i;      // 0..511
            int row = f >> 4;           // 0..31
            int c4  = (f & 15) * 4;     // 0..60
            float4 kv = *(const float4*)(kbase + (size_t)(l0 + row) * D_ + c4);
            kst[c4 + 0][row] = kv.x;
            kst[c4 + 1][row] = kv.y;
            kst[c4 + 2][row] = kv.z;
            kst[c4 + 3][row] = kv.w;
            *(float4*)&vs[row][c4] = *(const float4*)(vbase + (size_t)(l0 + row) * D_ + c4);
        }
        __syncthreads();

        // scores: warp w computes s[u][lane] for its 5 u's (l = l0+lane)
        {
            float s0 = 0.f, s1 = 0.f, s2 = 0.f, s3 = 0.f, s4 = 0.f;
#pragma unroll 16
            for (int d = 0; d < D_; d++) {
                float bb = kst[d][lane];
                s0 = fmaf(qs[w][d],      bb, s0);
                s1 = fmaf(qs[w + 8][d],  bb, s1);
                s2 = fmaf(qs[w + 16][d], bb, s2);
                s3 = fmaf(qs[w + 24][d], bb, s3);
                s4 = fmaf(qs[w + 32][d], bb, s4);
            }
            const int lg = l0 + lane;
            ss[w][lane]      = (lg > mt[w])      ? NEG_INF : s0 * 0.125f;
            ss[w + 8][lane]  = (lg > mt[w + 8])  ? NEG_INF : s1 * 0.125f;
            ss[w + 16][lane] = (lg > mt[w + 16]) ? NEG_INF : s2 * 0.125f;
            ss[w + 24][lane] = (lg > mt[w + 24]) ? NEG_INF : s3 * 0.125f;
            ss[w + 32][lane] = (lg > mt[w + 32]) ? NEG_INF : s4 * 0.125f;
        }
        __syncthreads();

        // online softmax: warp handles its 5 u rows (32 scores each)
#pragma unroll
        for (int j = 0; j < 5; j++) {
            const int u = w + 8 * j;
            float svv = ss[u][lane];
            float tm = svv;
#pragma unroll
            for (int o = 16; o > 0; o >>= 1) tm = fmaxf(tm, __shfl_xor_sync(0xffffffffu, tm, o));
            const float om = mrow[u];
            const float nm = fmaxf(om, tm);
            float p = __expf(svv - nm);
            ss[u][lane] = p;
            float sum = p;
#pragma unroll
            for (int o = 16; o > 0; o >>= 1) sum += __shfl_xor_sync(0xffffffffu, sum, o);
            if (lane == 0) {
                const float c = __expf(om - nm);
                srow[u] = srow[u] * c + sum;
                mrow[u] = nm;
                crow[u] = c;
            }
        }
        __syncthreads();

        // PV: accs[u][d] = accs[u][d]*crow[u] + sum_l p[u][l] * v[l][d]
#pragma unroll
        for (int j = 0; j < 5; j++) {
            const int u = w + 8 * j;
            const float c = crow[u];
            float a0 = accs[u][2 * lane]     * c;
            float a1 = accs[u][2 * lane + 1] * c;
#pragma unroll 8
            for (int l = 0; l < 32; l++) {
                const float p = ss[u][l];
                a0 = fmaf(p, vs[l][2 * lane],     a0);
                a1 = fmaf(p, vs[l][2 * lane + 1], a1);
            }
            accs[u][2 * lane]     = a0;
            accs[u][2 * lane + 1] = a1;
        }
    }
    __syncthreads();

    // scatter: context rows m_top[u] <- accs[u]/srow[u]
    for (int i = t; i < U_ * D_; i += 256) {
        int u = i >> 6, d = i & 63;
        g_ctx[((size_t)bh * L_ + mt[u]) * D_ + d] = accs[u][d] / srow[u];
    }
}

// ---------------------------------------------------------------------------
// Kernel 6: out = ctx(32768x512) @ Wo(512x64).  64x64 tile, BK=32, 4x4 micro.
// ---------------------------------------------------------------------------
__global__ __launch_bounds__(256) void out_gemm(const float* __restrict__ Wo,
                                                float* __restrict__ out)
{
    __shared__ float As[32][64];   // transposed ctx tile
    __shared__ float Bs[32][64];

    const int t  = threadIdx.x;
    const int tx = t & 15;
    const int ty = t >> 4;
    const size_t m0 = (size_t)blockIdx.x * 64;

    float acc[4][4];
#pragma unroll
    for (int i = 0; i < 4; i++)
#pragma unroll
        for (int j = 0; j < 4; j++) acc[i][j] = 0.f;

    for (int kb = 0; kb < HID_; kb += 32) {
        __syncthreads();
#pragma unroll
        for (int i = 0; i < 2; i++) {
            int f    = t + 256 * i;      // 0..511
            int arow = f >> 3;           // 0..63
            int ac4  = (f & 7) * 4;      // 0..28
            float4 av = *(const float4*)(g_ctx + (m0 + arow) * HID_ + kb + ac4);
            As[ac4 + 0][arow] = av.x;
            As[ac4 + 1][arow] = av.y;
            As[ac4 + 2][arow] = av.z;
            As[ac4 + 3][arow] = av.w;
            int brow = f >> 4;           // 0..31
            int bc4  = (f & 15) * 4;     // 0..60
            *(float4*)&Bs[brow][bc4] = *(const float4*)(Wo + (size_t)(kb + brow) * 64 + bc4);
        }
        __syncthreads();
#pragma unroll
        for (int k = 0; k < 32; k++) {
            float a[4], b[4];
            *(float4*)a = *(const float4*)&As[k][ty * 4];
            *(float4*)b = *(const float4*)&Bs[k][tx * 4];
#pragma unroll
            for (int i = 0; i < 4; i++)
#pragma unroll
                for (int j = 0; j < 4; j++)
                    acc[i][j] = fmaf(a[i], b[j], acc[i][j]);
        }
    }

#pragma unroll
    for (int i = 0; i < 4; i++) {
        float4 o = make_float4(acc[i][0], acc[i][1], acc[i][2], acc[i][3]);
        *(float4*)(out + (m0 + ty * 4 + i) * 64 + tx * 4) = o;
    }
}

// ---------------------------------------------------------------------------
extern "C" void kernel_launch(void* const* d_in, const int* in_sizes, int n_in,
                              void* d_out, int out_size)
{
    (void)in_sizes; (void)n_in; (void)out_size;
    const float* q_in = (const float*)d_in[0];
    const float* k_in = (const float*)d_in[1];
    const float* v_in = (const float*)d_in[2];
    const float* Wq   = (const float*)d_in[3];
    const float* Wk   = (const float*)d_in[4];
    const float* Wv   = (const float*)d_in[5];
    const float* Wo   = (const float*)d_in[6];
    const int*   idx  = (const int*)d_in[7];
    float* out = (float*)d_out;

    dim3 gqkv(HID_ / 128, MROWS / 128, 3);
    sgemm_qkv<<<gqkv, 256>>>(q_in, k_in, v_in, Wq, Wk, Wv);
    dot_kernel<<<(BH_ * L_) / 8, 256>>>(idx);
    topk_kernel<<<BH_, 256>>>();
    cumsum_kernel<<<BH_, 64>>>();
    attn_kernel<<<BH_, 256>>>();
    out_gemm<<<MROWS / 64, 256>>>(Wo, out);
}

// round 3
// speedup vs baseline: 1.5270x; 1.5270x over previous
#include <cuda_runtime.h>
#include <math.h>

// ---------------------------------------------------------------------------
// ProbAttention (Informer ProbSparse) — fp32, round 3 (resubmit of R2 after
// infra failure). Shapes: B=16, L=2048, D_IN=512, HID=512, H=8, D=64, U=40
// ---------------------------------------------------------------------------

#define B_    16
#define L_    2048
#define DIN_  512
#define HID_  512
#define H_    8
#define D_    64
#define U_    40
#define BH_   (B_ * H_)      // 128
#define MROWS (B_ * L_)      // 32768

#define NEG_INF (__int_as_float(0xff800000))

// Scratch (no cudaMalloc allowed): ~268 MB of device globals.
__device__ float g_q[(size_t)MROWS * HID_];
__device__ float g_k[(size_t)MROWS * HID_];
__device__ float g_v[(size_t)MROWS * HID_];
__device__ float g_ctx[(size_t)MROWS * HID_];
__device__ float g_dot[BH_ * L_];
__device__ int   g_mtop[BH_ * U_];

// ---------------------------------------------------------------------------
// Kernel 1: QKV projection GEMMs.  C = A(32768x512) @ W(512x512), z in {q,k,v}
// 128x128 block tile, BK=8, 256 threads, 8x8 microtile, register prefetch.
// ---------------------------------------------------------------------------
__global__ __launch_bounds__(256) void sgemm_qkv(
    const float* __restrict__ Aq, const float* __restrict__ Ak, const float* __restrict__ Av,
    const float* __restrict__ Wq, const float* __restrict__ Wk, const float* __restrict__ Wv)
{
    const float* A; const float* W; float* C;
    if (blockIdx.z == 0)      { A = Aq; W = Wq; C = g_q; }
    else if (blockIdx.z == 1) { A = Ak; W = Wk; C = g_k; }
    else                      { A = Av; W = Wv; C = g_v; }

    __shared__ float As[8][128];   // transposed A tile
    __shared__ float Bs[8][128];

    const int t  = threadIdx.x;
    const int tx = t & 15;         // N direction (x8)
    const int ty = t >> 4;         // M direction (x8)

    const int arow = t >> 1;          // 0..127
    const int akk  = (t & 1) * 4;     // 0 or 4
    const int brow = t >> 5;          // 0..7
    const int bcol = (t & 31) * 4;    // 0..124

    const size_t m0 = (size_t)blockIdx.y * 128;
    const int    n0 = blockIdx.x * 128;

    const float* Ap = A + (m0 + arow) * DIN_ + akk;
    const float* Wp = W + (size_t)brow * HID_ + n0 + bcol;

    float acc[8][8];
#pragma unroll
    for (int i = 0; i < 8; i++)
#pragma unroll
        for (int j = 0; j < 8; j++) acc[i][j] = 0.f;

    // prefetch tile 0 into registers
    float4 av = *(const float4*)(Ap);
    float4 bv = *(const float4*)(Wp);

    for (int kb = 0; kb < DIN_; kb += 8) {
        __syncthreads();
        As[akk + 0][arow] = av.x;
        As[akk + 1][arow] = av.y;
        As[akk + 2][arow] = av.z;
        As[akk + 3][arow] = av.w;
        *(float4*)&Bs[brow][bcol] = bv;
        __syncthreads();
        // issue next tile's loads before compute (latency hidden under FMAs)
        if (kb + 8 < DIN_) {
            av = *(const float4*)(Ap + kb + 8);
            bv = *(const float4*)(Wp + (size_t)(kb + 8) * HID_);
        }
#pragma unroll
        for (int k = 0; k < 8; k++) {
            float a[8], b[8];
            *(float4*)&a[0] = *(const float4*)&As[k][ty * 8];
            *(float4*)&a[4] = *(const float4*)&As[k][ty * 8 + 4];
            *(float4*)&b[0] = *(const float4*)&Bs[k][tx * 8];
            *(float4*)&b[4] = *(const float4*)&Bs[k][tx * 8 + 4];
#pragma unroll
            for (int i = 0; i < 8; i++)
#pragma unroll
                for (int j = 0; j < 8; j++)
                    acc[i][j] = fmaf(a[i], b[j], acc[i][j]);
        }
    }

#pragma unroll
    for (int i = 0; i < 8; i++) {
        float* crow = C + (m0 + ty * 8 + i) * HID_ + n0 + tx * 8;
        float4 o0 = make_float4(acc[i][0], acc[i][1], acc[i][2], acc[i][3]);
        float4 o1 = make_float4(acc[i][4], acc[i][5], acc[i][6], acc[i][7]);
        *(float4*)crow       = o0;
        *(float4*)(crow + 4) = o1;
    }
}

// ---------------------------------------------------------------------------
// Kernel 2: dot[bh,l] = q[bh,l,:] . k[bh,idx[l],:]   (one warp per (bh,l))
// ---------------------------------------------------------------------------
__global__ __launch_bounds__(256) void dot_kernel(const int* __restrict__ idx)
{
    const int gid  = blockIdx.x * blockDim.x + threadIdx.x;
    const int warp = gid >> 5;
    const int lane = gid & 31;
    const int l  = warp & (L_ - 1);
    const int bh = warp >> 11;     // L_=2048 -> shift 11

    const float* qrow = g_q + ((size_t)bh * L_ + l) * D_;
    const float* krow = g_k + ((size_t)bh * L_ + idx[l]) * D_;
    float s = qrow[lane] * krow[lane] + qrow[lane + 32] * krow[lane + 32];
#pragma unroll
    for (int o = 16; o > 0; o >>= 1) s += __shfl_xor_sync(0xffffffffu, s, o);
    if (lane == 0) g_dot[warp] = s;
}

// ---------------------------------------------------------------------------
// Kernel 3: top-U indices of dot[bh,:] (monotonic scale => same set as ref's M)
// One block per bh; U iterative argmax passes with tie -> smaller index.
// ---------------------------------------------------------------------------
__global__ __launch_bounds__(256) void topk_kernel()
{
    const int bh = blockIdx.x;
    const int t  = threadIdx.x;
    __shared__ float sv[L_];
    __shared__ float rv[256];
    __shared__ int   ri[256];

    for (int i = t; i < L_; i += 256) sv[i] = g_dot[bh * L_ + i];
    __syncthreads();

    for (int p = 0; p < U_; p++) {
        float bvv = NEG_INF;
        int   bii = 0x7fffffff;
        for (int i = t; i < L_; i += 256) {
            float v = sv[i];
            if (v > bvv || (v == bvv && i < bii)) { bvv = v; bii = i; }
        }
        rv[t] = bvv; ri[t] = bii;
        __syncthreads();
        for (int s = 128; s > 0; s >>= 1) {
            if (t < s) {
                if (rv[t + s] > rv[t] || (rv[t + s] == rv[t] && ri[t + s] < ri[t])) {
                    rv[t] = rv[t + s]; ri[t] = ri[t + s];
                }
            }
            __syncthreads();
        }
        if (t == 0) {
            g_mtop[bh * U_ + p] = ri[0];
            sv[ri[0]] = NEG_INF;
        }
        __syncthreads();
    }
}

// ---------------------------------------------------------------------------
// Kernel 4: context = cumsum(v, axis=L).  Parallel two-pass scan.
// One block (1024 threads) per bh. thread t -> (seg = t>>6 in 0..15, d = t&63).
// Pass 1: per-segment sums; smem exclusive scan over segments; pass 2: replay.
// Consecutive threads = consecutive d -> fully coalesced 256B rows.
// ---------------------------------------------------------------------------
#define CSEG   16
#define CSEGL  (L_ / CSEG)   // 128

__global__ __launch_bounds__(1024) void cumsum_kernel()
{
    const int bh  = blockIdx.x;
    const int t   = threadIdx.x;
    const int d   = t & 63;
    const int seg = t >> 6;          // 0..15

    const float* vp = g_v   + (size_t)bh * L_ * D_ + (size_t)seg * CSEGL * D_ + d;
    float*       cp = g_ctx + (size_t)bh * L_ * D_ + (size_t)seg * CSEGL * D_ + d;

    // pass 1: segment sum (independent loads, high MLP)
    float s = 0.f;
#pragma unroll 8
    for (int l = 0; l < CSEGL; l++) s += vp[(size_t)l * D_];

    __shared__ float segsum[CSEG][D_ + 1];
    segsum[seg][d] = s;
    __syncthreads();

    // exclusive prefix over segments for this d
    float off = 0.f;
#pragma unroll
    for (int s2 = 0; s2 < CSEG; s2++) {
        if (s2 < seg) off += segsum[s2][d];
    }

    // pass 2: replay with offset
    float acc = off;
#pragma unroll 8
    for (int l = 0; l < CSEGL; l++) {
        acc += vp[(size_t)l * D_];
        cp[(size_t)l * D_] = acc;
    }
}

// ---------------------------------------------------------------------------
// Kernel 5: flash-style attention for the U=40 selected queries per (bh),
// causal mask l > m_top[u], online softmax; scatter result into g_ctx rows.
// One block (256 threads = 8 warps) per bh. Warp w owns u in {w, w+8, ..., w+32}.
// ---------------------------------------------------------------------------
__global__ __launch_bounds__(256) void attn_kernel()
{
    const int bh   = blockIdx.x;
    const int t    = threadIdx.x;
    const int lane = t & 31;
    const int w    = t >> 5;

    __shared__ float qs[U_][D_];      // selected queries
    __shared__ float kst[D_][32];     // k tile, transposed [d][l]
    __shared__ float vs[32][D_];      // v tile [l][d]
    __shared__ float ss[U_][32];      // scores / probs
    __shared__ float accs[U_][D_];    // output accumulators
    __shared__ float mrow[U_], srow[U_], crow[U_];
    __shared__ int   mt[U_];

    if (t < U_) {
        mt[t]   = g_mtop[bh * U_ + t];
        mrow[t] = NEG_INF;
        srow[t] = 0.f;
    }
    __syncthreads();

    for (int i = t; i < U_ * D_; i += 256) {
        int u = i >> 6, d = i & 63;
        qs[u][d]   = g_q[((size_t)bh * L_ + mt[u]) * D_ + d];
        accs[u][d] = 0.f;
    }

    const float* kbase = g_k + (size_t)bh * L_ * D_;
    const float* vbase = g_v + (size_t)bh * L_ * D_;

    for (int tile = 0; tile < L_ / 32; tile++) {
        const int l0 = tile * 32;
        __syncthreads();   // prev PV done reading vs/ss; qs/accs init done on tile 0
        // load k (transposed) + v tiles: 32 rows x 64 cols, float4 per thread x2
#pragma unroll
        for (int i = 0; i < 2; i++) {
            int f   = t + 256 * i;      // 0..511
            int row = f >> 4;           // 0..31
            int c4  = (f & 15) * 4;     // 0..60
            float4 kv = *(const float4*)(kbase + (size_t)(l0 + row) * D_ + c4);
            kst[c4 + 0][row] = kv.x;
            kst[c4 + 1][row] = kv.y;
            kst[c4 + 2][row] = kv.z;
            kst[c4 + 3][row] = kv.w;
            *(float4*)&vs[row][c4] = *(const float4*)(vbase + (size_t)(l0 + row) * D_ + c4);
        }
        __syncthreads();

        // scores: warp w computes s[u][lane] for its 5 u's (l = l0+lane)
        {
            float s0 = 0.f, s1 = 0.f, s2 = 0.f, s3 = 0.f, s4 = 0.f;
#pragma unroll 16
            for (int d = 0; d < D_; d++) {
                float bb = kst[d][lane];
                s0 = fmaf(qs[w][d],      bb, s0);
                s1 = fmaf(qs[w + 8][d],  bb, s1);
                s2 = fmaf(qs[w + 16][d], bb, s2);
                s3 = fmaf(qs[w + 24][d], bb, s3);
                s4 = fmaf(qs[w + 32][d], bb, s4);
            }
            const int lg = l0 + lane;
            ss[w][lane]      = (lg > mt[w])      ? NEG_INF : s0 * 0.125f;
            ss[w + 8][lane]  = (lg > mt[w + 8])  ? NEG_INF : s1 * 0.125f;
            ss[w + 16][lane] = (lg > mt[w + 16]) ? NEG_INF : s2 * 0.125f;
            ss[w + 24][lane] = (lg > mt[w + 24]) ? NEG_INF : s3 * 0.125f;
            ss[w + 32][lane] = (lg > mt[w + 32]) ? NEG_INF : s4 * 0.125f;
        }
        __syncthreads();

        // online softmax: warp handles its 5 u rows (32 scores each)
#pragma unroll
        for (int j = 0; j < 5; j++) {
            const int u = w + 8 * j;
            float svv = ss[u][lane];
            float tm = svv;
#pragma unroll
            for (int o = 16; o > 0; o >>= 1) tm = fmaxf(tm, __shfl_xor_sync(0xffffffffu, tm, o));
            const float om = mrow[u];
            const float nm = fmaxf(om, tm);
            float p = __expf(svv - nm);
            ss[u][lane] = p;
            float sum = p;
#pragma unroll
            for (int o = 16; o > 0; o >>= 1) sum += __shfl_xor_sync(0xffffffffu, sum, o);
            if (lane == 0) {
                const float c = __expf(om - nm);
                srow[u] = srow[u] * c + sum;
                mrow[u] = nm;
                crow[u] = c;
            }
        }
        __syncthreads();

        // PV: accs[u][d] = accs[u][d]*crow[u] + sum_l p[u][l] * v[l][d]
#pragma unroll
        for (int j = 0; j < 5; j++) {
            const int u = w + 8 * j;
            const float c = crow[u];
            float a0 = accs[u][2 * lane]     * c;
            float a1 = accs[u][2 * lane + 1] * c;
#pragma unroll 8
            for (int l = 0; l < 32; l++) {
                const float p = ss[u][l];
                a0 = fmaf(p, vs[l][2 * lane],     a0);
                a1 = fmaf(p, vs[l][2 * lane + 1], a1);
            }
            accs[u][2 * lane]     = a0;
            accs[u][2 * lane + 1] = a1;
        }
    }
    __syncthreads();

    // scatter: context rows m_top[u] <- accs[u]/srow[u]
    for (int i = t; i < U_ * D_; i += 256) {
        int u = i >> 6, d = i & 63;
        g_ctx[((size_t)bh * L_ + mt[u]) * D_ + d] = accs[u][d] / srow[u];
    }
}

// ---------------------------------------------------------------------------
// Kernel 6: out = ctx(32768x512) @ Wo(512x64).  64x64 tile, BK=32, 4x4 micro.
// ---------------------------------------------------------------------------
__global__ __launch_bounds__(256) void out_gemm(const float* __restrict__ Wo,
                                                float* __restrict__ out)
{
    __shared__ float As[32][64];   // transposed ctx tile
    __shared__ float Bs[32][64];

    const int t  = threadIdx.x;
    const int tx = t & 15;
    const int ty = t >> 4;
    const size_t m0 = (size_t)blockIdx.x * 64;

    float acc[4][4];
#pragma unroll
    for (int i = 0; i < 4; i++)
#pragma unroll
        for (int j = 0; j < 4; j++) acc[i][j] = 0.f;

    for (int kb = 0; kb < HID_; kb += 32) {
        __syncthreads();
#pragma unroll
        for (int i = 0; i < 2; i++) {
            int f    = t + 256 * i;      // 0..511
            int arow = f >> 3;           // 0..63
            int ac4  = (f & 7) * 4;      // 0..28
            float4 av = *(const float4*)(g_ctx + (m0 + arow) * HID_ + kb + ac4);
            As[ac4 + 0][arow] = av.x;
            As[ac4 + 1][arow] = av.y;
            As[ac4 + 2][arow] = av.z;
            As[ac4 + 3][arow] = av.w;
            int brow = f >> 4;           // 0..31
            int bc4  = (f & 15) * 4;     // 0..60
            *(float4*)&Bs[brow][bc4] = *(const float4*)(Wo + (size_t)(kb + brow) * 64 + bc4);
        }
        __syncthreads();
#pragma unroll
        for (int k = 0; k < 32; k++) {
            float a[4], b[4];
            *(float4*)a = *(const float4*)&As[k][ty * 4];
            *(float4*)b = *(const float4*)&Bs[k][tx * 4];
#pragma unroll
            for (int i = 0; i < 4; i++)
#pragma unroll
                for (int j = 0; j < 4; j++)
                    acc[i][j] = fmaf(a[i], b[j], acc[i][j]);
        }
    }

#pragma unroll
    for (int i = 0; i < 4; i++) {
        float4 o = make_float4(acc[i][0], acc[i][1], acc[i][2], acc[i][3]);
        *(float4*)(out + (m0 + ty * 4 + i) * 64 + tx * 4) = o;
    }
}

// ---------------------------------------------------------------------------
extern "C" void kernel_launch(void* const* d_in, const int* in_sizes, int n_in,
                              void* d_out, int out_size)
{
    (void)in_sizes; (void)n_in; (void)out_size;
    const float* q_in = (const float*)d_in[0];
    const float* k_in = (const float*)d_in[1];
    const float* v_in = (const float*)d_in[2];
    const float* Wq   = (const float*)d_in[3];
    const float* Wk   = (const float*)d_in[4];
    const float* Wv   = (const float*)d_in[5];
    const float* Wo   = (const float*)d_in[6];
    const int*   idx  = (const int*)d_in[7];
    float* out = (float*)d_out;

    dim3 gqkv(HID_ / 128, MROWS / 128, 3);
    sgemm_qkv<<<gqkv, 256>>>(q_in, k_in, v_in, Wq, Wk, Wv);
    dot_kernel<<<(BH_ * L_) / 8, 256>>>(idx);
    topk_kernel<<<BH_, 256>>>();
    cumsum_kernel<<<BH_, 1024>>>();
    attn_kernel<<<BH_, 256>>>();
    out_gemm<<<MROWS / 64, 256>>>(Wo, out);
}

// round 6
// speedup vs baseline: 2.1682x; 1.4199x over previous
#include <cuda_runtime.h>
#include <cuda_fp16.h>
#include <math.h>

// ---------------------------------------------------------------------------
// ProbAttention (Informer ProbSparse) — round 5: mma.sync fp16-split QKV GEMM
// (tcgen05 unavailable: harness compiles PTX at base sm_100 target)
// Shapes: B=16, L=2048, D_IN=512, HID=512, H=8, D=64, U=40
// ---------------------------------------------------------------------------

#define B_    16
#define L_    2048
#define DIN_  512
#define HID_  512
#define H_    8
#define D_    64
#define U_    40
#define BH_   (B_ * H_)      // 128
#define MROWS (B_ * L_)      // 32768

#define NEG_INF (__int_as_float(0xff800000))

// Scratch (no cudaMalloc allowed): device globals.
__device__ float g_q[(size_t)MROWS * HID_];
__device__ float g_k[(size_t)MROWS * HID_];
__device__ float g_v[(size_t)MROWS * HID_];
__device__ float g_ctx[(size_t)MROWS * HID_];
__device__ float g_dot[BH_ * L_];
__device__ int   g_mtop[BH_ * U_];
// fp16 split operands (hi/lo) for the 3 input matrices and 3 weight matrices
__device__ __half g_ah[(size_t)3 * MROWS * DIN_];
__device__ __half g_al[(size_t)3 * MROWS * DIN_];
__device__ __half g_wh[(size_t)3 * DIN_ * HID_];   // [g][n][k] (W transposed)
__device__ __half g_wl[(size_t)3 * DIN_ * HID_];

// ---------------------------------------------------------------------------
// PTX helpers (base-target: ldmatrix + mma.sync, sm_80+)
// ---------------------------------------------------------------------------
__device__ __forceinline__ unsigned smem_u32(const void* p) {
    unsigned a;
    asm("{ .reg .u64 t; cvta.to.shared.u64 t, %1; cvt.u32.u64 %0, t; }"
        : "=r"(a) : "l"(p));
    return a;
}

__device__ __forceinline__ void ldsm_x4(unsigned& r0, unsigned& r1,
                                        unsigned& r2, unsigned& r3, unsigned a) {
    asm volatile("ldmatrix.sync.aligned.m8n8.x4.shared.b16 {%0,%1,%2,%3}, [%4];"
                 : "=r"(r0), "=r"(r1), "=r"(r2), "=r"(r3) : "r"(a));
}

__device__ __forceinline__ void mma16816(float* d, const unsigned* a, const unsigned* b) {
    asm volatile(
        "mma.sync.aligned.m16n8k16.row.col.f32.f16.f16.f32 "
        "{%0,%1,%2,%3}, {%4,%5,%6,%7}, {%8,%9}, {%0,%1,%2,%3};"
        : "+f"(d[0]), "+f"(d[1]), "+f"(d[2]), "+f"(d[3])
        : "r"(a[0]), "r"(a[1]), "r"(a[2]), "r"(a[3]), "r"(b[0]), "r"(b[1]));
}

// ---------------------------------------------------------------------------
// Kernel 0a: fp32 -> fp16 hi/lo split of the three input matrices
// ---------------------------------------------------------------------------
__global__ __launch_bounds__(256) void split_in(
    const float* __restrict__ q, const float* __restrict__ k, const float* __restrict__ v)
{
    const int g = blockIdx.y;
    const float* src = (g == 0) ? q : (g == 1) ? k : v;
    size_t base = ((size_t)blockIdx.x * 256 + threadIdx.x) * 4;
    float4 x = *(const float4*)(src + base);
    __half h0 = __float2half_rn(x.x), h1 = __float2half_rn(x.y);
    __half h2 = __float2half_rn(x.z), h3 = __float2half_rn(x.w);
    __half l0 = __float2half_rn(x.x - __half2float(h0));
    __half l1 = __float2half_rn(x.y - __half2float(h1));
    __half l2 = __float2half_rn(x.z - __half2float(h2));
    __half l3 = __float2half_rn(x.w - __half2float(h3));
    __half2* ah = (__half2*)(g_ah + (size_t)g * MROWS * DIN_ + base);
    __half2* al = (__half2*)(g_al + (size_t)g * MROWS * DIN_ + base);
    ah[0] = __halves2half2(h0, h1); ah[1] = __halves2half2(h2, h3);
    al[0] = __halves2half2(l0, l1); al[1] = __halves2half2(l2, l3);
}

// ---------------------------------------------------------------------------
// Kernel 0b: weight split + transpose: g_w*[g][n][k] = split(W[k][n])
// ---------------------------------------------------------------------------
__global__ __launch_bounds__(256) void split_w(
    const float* __restrict__ Wq, const float* __restrict__ Wk, const float* __restrict__ Wv)
{
    const int g = blockIdx.y;
    const float* W = (g == 0) ? Wq : (g == 1) ? Wk : Wv;
    int o = blockIdx.x * 256 + threadIdx.x;     // 0..262143
    int n = o >> 9, kd = o & 511;
    float x = W[(size_t)kd * HID_ + n];
    __half h = __float2half_rn(x);
    g_wh[(size_t)g * DIN_ * HID_ + o] = h;
    g_wl[(size_t)g * DIN_ * HID_ + o] = __float2half_rn(x - __half2float(h));
}

// ---------------------------------------------------------------------------
// Kernel 1: QKV GEMM via mma.sync (HMMA), fp16 3-term split (K' = 1536).
// CTA tile 128x128, 8 warps in 4(M)x2(N), warp tile 32x64.
// BK=32 per stage, smem pad stride 40 halves (conflict-free ldmatrix),
// register-prefetch double buffering.
// ---------------------------------------------------------------------------
__global__ __launch_bounds__(256, 2) void gemm_qkv_mma()
{
    __shared__ __align__(16) __half As[128][40];
    __shared__ __align__(16) __half Bs[128][40];

    const int t    = threadIdx.x;
    const int lane = t & 31;
    const int wid  = t >> 5;
    const int g    = blockIdx.z;
    const size_t m0 = (size_t)blockIdx.y * 128;
    const int    n0 = blockIdx.x * 128;
    const int wm = wid >> 1;      // 0..3 -> M offset wm*32
    const int wn = wid & 1;       // 0..1 -> N offset wn*64

    const __half* ah = g_ah + (size_t)g * MROWS * DIN_;
    const __half* al = g_al + (size_t)g * MROWS * DIN_;
    const __half* wh = g_wh + (size_t)g * DIN_ * HID_;
    const __half* wl = g_wl + (size_t)g * DIN_ * HID_;

    // loader geometry: thread handles rows lrow and lrow+64, 16B at col lcol
    const int lrow = t >> 2;            // 0..63
    const int lcol = (t & 3) * 8;       // fp16 col: 0,8,16,24

    // ldmatrix per-lane address bases (byte addresses into smem)
    const unsigned sA = smem_u32(As);
    const unsigned sB = smem_u32(Bs);
    const unsigned aBase = sA + (unsigned)(wm * 32 + (lane & 15)) * 80u
                              + (unsigned)(lane >> 4) * 16u;
    const unsigned bBase = sB + (unsigned)(wn * 64 + (lane & 7) + ((lane >> 4) & 1) * 8) * 80u
                              + (unsigned)((lane >> 3) & 1) * 16u;

    float acc[2][8][4];
#pragma unroll
    for (int i = 0; i < 2; i++)
#pragma unroll
        for (int j = 0; j < 8; j++)
#pragma unroll
            for (int r = 0; r < 4; r++) acc[i][j][r] = 0.f;

    // prefetch chunk 0 (phase 0: Ah, Wh; kk = 0)
    uint4 pa0 = *(const uint4*)(ah + (m0 + lrow) * DIN_ + lcol);
    uint4 pa1 = *(const uint4*)(ah + (m0 + lrow + 64) * DIN_ + lcol);
    uint4 pb0 = *(const uint4*)(wh + (size_t)(n0 + lrow) * DIN_ + lcol);
    uint4 pb1 = *(const uint4*)(wh + (size_t)(n0 + lrow + 64) * DIN_ + lcol);

    for (int c = 0; c < 48; c++) {
        __syncthreads();
        *(uint4*)&As[lrow][lcol]      = pa0;
        *(uint4*)&As[lrow + 64][lcol] = pa1;
        *(uint4*)&Bs[lrow][lcol]      = pb0;
        *(uint4*)&Bs[lrow + 64][lcol] = pb1;
        __syncthreads();

        if (c + 1 < 48) {
            const int cn = c + 1;
            const int phase = cn >> 4;           // 0: Ah*Bh, 1: Ah*Bl, 2: Al*Bh
            const int kk = (cn & 15) * 32;
            const __half* A  = (phase == 2) ? al : ah;
            const __half* Bm = (phase == 1) ? wl : wh;
            pa0 = *(const uint4*)(A + (m0 + lrow) * DIN_ + kk + lcol);
            pa1 = *(const uint4*)(A + (m0 + lrow + 64) * DIN_ + kk + lcol);
            pb0 = *(const uint4*)(Bm + (size_t)(n0 + lrow) * DIN_ + kk + lcol);
            pb1 = *(const uint4*)(Bm + (size_t)(n0 + lrow + 64) * DIN_ + kk + lcol);
        }

#pragma unroll
        for (int ks = 0; ks < 2; ks++) {
            unsigned a0[4], a1[4];
            ldsm_x4(a0[0], a0[1], a0[2], a0[3], aBase + ks * 32u);
            ldsm_x4(a1[0], a1[1], a1[2], a1[3], aBase + 1280u + ks * 32u);  // +16 rows
#pragma unroll
            for (int tj2 = 0; tj2 < 4; tj2++) {
                unsigned b[4];
                ldsm_x4(b[0], b[1], b[2], b[3], bBase + (unsigned)tj2 * 1280u + ks * 32u);
                // b[0..1] = n-tile 2*tj2, b[2..3] = n-tile 2*tj2+1
                mma16816(acc[0][2 * tj2],     a0, &b[0]);
                mma16816(acc[1][2 * tj2],     a1, &b[0]);
                mma16816(acc[0][2 * tj2 + 1], a0, &b[2]);
                mma16816(acc[1][2 * tj2 + 1], a1, &b[2]);
            }
        }
    }

    // epilogue: direct fp32 stores (float2 per d-pair)
    float* C = (g == 0) ? g_q : (g == 1) ? g_k : g_v;
#pragma unroll
    for (int ti = 0; ti < 2; ti++) {
#pragma unroll
        for (int tj = 0; tj < 8; tj++) {
            const size_t row = m0 + wm * 32 + ti * 16 + (lane >> 2);
            const int    col = n0 + wn * 64 + tj * 8 + (lane & 3) * 2;
            *(float2*)(C + row * HID_ + col) =
                make_float2(acc[ti][tj][0], acc[ti][tj][1]);
            *(float2*)(C + (row + 8) * HID_ + col) =
                make_float2(acc[ti][tj][2], acc[ti][tj][3]);
        }
    }
}

// ---------------------------------------------------------------------------
// Kernel 2: dot[bh,l] = q[bh,l,:] . k[bh,idx[l],:]   (one warp per (bh,l))
// ---------------------------------------------------------------------------
__global__ __launch_bounds__(256) void dot_kernel(const int* __restrict__ idx)
{
    const int gid  = blockIdx.x * blockDim.x + threadIdx.x;
    const int warp = gid >> 5;
    const int lane = gid & 31;
    const int l  = warp & (L_ - 1);
    const int bh = warp >> 11;

    const float* qrow = g_q + ((size_t)bh * L_ + l) * D_;
    const float* krow = g_k + ((size_t)bh * L_ + idx[l]) * D_;
    float s = qrow[lane] * krow[lane] + qrow[lane + 32] * krow[lane + 32];
#pragma unroll
    for (int o = 16; o > 0; o >>= 1) s += __shfl_xor_sync(0xffffffffu, s, o);
    if (lane == 0) g_dot[warp] = s;
}

// ---------------------------------------------------------------------------
// Kernel 3: top-U indices of dot[bh,:]
// ---------------------------------------------------------------------------
__global__ __launch_bounds__(256) void topk_kernel()
{
    const int bh = blockIdx.x;
    const int t  = threadIdx.x;
    __shared__ float sv[L_];
    __shared__ float rv[256];
    __shared__ int   ri[256];

    for (int i = t; i < L_; i += 256) sv[i] = g_dot[bh * L_ + i];
    __syncthreads();

    for (int p = 0; p < U_; p++) {
        float bvv = NEG_INF;
        int   bii = 0x7fffffff;
        for (int i = t; i < L_; i += 256) {
            float v = sv[i];
            if (v > bvv || (v == bvv && i < bii)) { bvv = v; bii = i; }
        }
        rv[t] = bvv; ri[t] = bii;
        __syncthreads();
        for (int s = 128; s > 0; s >>= 1) {
            if (t < s) {
                if (rv[t + s] > rv[t] || (rv[t + s] == rv[t] && ri[t + s] < ri[t])) {
                    rv[t] = rv[t + s]; ri[t] = ri[t + s];
                }
            }
            __syncthreads();
        }
        if (t == 0) {
            g_mtop[bh * U_ + p] = ri[0];
            sv[ri[0]] = NEG_INF;
        }
        __syncthreads();
    }
}

// ---------------------------------------------------------------------------
// Kernel 4: context = cumsum(v, axis=L).  Parallel two-pass scan.
// ---------------------------------------------------------------------------
#define CSEG   16
#define CSEGL  (L_ / CSEG)   // 128

__global__ __launch_bounds__(1024) void cumsum_kernel()
{
    const int bh  = blockIdx.x;
    const int t   = threadIdx.x;
    const int d   = t & 63;
    const int seg = t >> 6;

    const float* vp = g_v   + (size_t)bh * L_ * D_ + (size_t)seg * CSEGL * D_ + d;
    float*       cp = g_ctx + (size_t)bh * L_ * D_ + (size_t)seg * CSEGL * D_ + d;

    float s = 0.f;
#pragma unroll 8
    for (int l = 0; l < CSEGL; l++) s += vp[(size_t)l * D_];

    __shared__ float segsum[CSEG][D_ + 1];
    segsum[seg][d] = s;
    __syncthreads();

    float off = 0.f;
#pragma unroll
    for (int s2 = 0; s2 < CSEG; s2++) {
        if (s2 < seg) off += segsum[s2][d];
    }

    float acc = off;
#pragma unroll 8
    for (int l = 0; l < CSEGL; l++) {
        acc += vp[(size_t)l * D_];
        cp[(size_t)l * D_] = acc;
    }
}

// ---------------------------------------------------------------------------
// Kernel 5: flash-style attention over the U=40 selected queries per (bh)
// ---------------------------------------------------------------------------
__global__ __launch_bounds__(256) void attn_kernel()
{
    const int bh   = blockIdx.x;
    const int t    = threadIdx.x;
    const int lane = t & 31;
    const int w    = t >> 5;

    __shared__ float qs[U_][D_];
    __shared__ float kst[D_][32];
    __shared__ float vs[32][D_];
    __shared__ float ss[U_][32];
    __shared__ float accs[U_][D_];
    __shared__ float mrow[U_], srow[U_], crow[U_];
    __shared__ int   mt[U_];

    if (t < U_) {
        mt[t]   = g_mtop[bh * U_ + t];
        mrow[t] = NEG_INF;
        srow[t] = 0.f;
    }
    __syncthreads();

    for (int i = t; i < U_ * D_; i += 256) {
        int u = i >> 6, d = i & 63;
        qs[u][d]   = g_q[((size_t)bh * L_ + mt[u]) * D_ + d];
        accs[u][d] = 0.f;
    }

    const float* kbase = g_k + (size_t)bh * L_ * D_;
    const float* vbase = g_v + (size_t)bh * L_ * D_;

    for (int tile = 0; tile < L_ / 32; tile++) {
        const int l0 = tile * 32;
        __syncthreads();
#pragma unroll
        for (int i = 0; i < 2; i++) {
            int f   = t + 256 * i;
            int row = f >> 4;
            int c4  = (f & 15) * 4;
            float4 kv = *(const float4*)(kbase + (size_t)(l0 + row) * D_ + c4);
            kst[c4 + 0][row] = kv.x;
            kst[c4 + 1][row] = kv.y;
            kst[c4 + 2][row] = kv.z;
            kst[c4 + 3][row] = kv.w;
            *(float4*)&vs[row][c4] = *(const float4*)(vbase + (size_t)(l0 + row) * D_ + c4);
        }
        __syncthreads();

        {
            float s0 = 0.f, s1 = 0.f, s2 = 0.f, s3 = 0.f, s4 = 0.f;
#pragma unroll 16
            for (int d = 0; d < D_; d++) {
                float bb = kst[d][lane];
                s0 = fmaf(qs[w][d],      bb, s0);
                s1 = fmaf(qs[w + 8][d],  bb, s1);
                s2 = fmaf(qs[w + 16][d], bb, s2);
                s3 = fmaf(qs[w + 24][d], bb, s3);
                s4 = fmaf(qs[w + 32][d], bb, s4);
            }
            const int lg = l0 + lane;
            ss[w][lane]      = (lg > mt[w])      ? NEG_INF : s0 * 0.125f;
            ss[w + 8][lane]  = (lg > mt[w + 8])  ? NEG_INF : s1 * 0.125f;
            ss[w + 16][lane] = (lg > mt[w + 16]) ? NEG_INF : s2 * 0.125f;
            ss[w + 24][lane] = (lg > mt[w + 24]) ? NEG_INF : s3 * 0.125f;
            ss[w + 32][lane] = (lg > mt[w + 32]) ? NEG_INF : s4 * 0.125f;
        }
        __syncthreads();

#pragma unroll
        for (int j = 0; j < 5; j++) {
            const int u = w + 8 * j;
            float svv = ss[u][lane];
            float tm = svv;
#pragma unroll
            for (int o = 16; o > 0; o >>= 1) tm = fmaxf(tm, __shfl_xor_sync(0xffffffffu, tm, o));
            const float om = mrow[u];
            const float nm = fmaxf(om, tm);
            float p = __expf(svv - nm);
            ss[u][lane] = p;
            float sum = p;
#pragma unroll
            for (int o = 16; o > 0; o >>= 1) sum += __shfl_xor_sync(0xffffffffu, sum, o);
            if (lane == 0) {
                const float c = __expf(om - nm);
                srow[u] = srow[u] * c + sum;
                mrow[u] = nm;
                crow[u] = c;
            }
        }
        __syncthreads();

#pragma unroll
        for (int j = 0; j < 5; j++) {
            const int u = w + 8 * j;
            const float c = crow[u];
            float a0 = accs[u][2 * lane]     * c;
            float a1 = accs[u][2 * lane + 1] * c;
#pragma unroll 8
            for (int l = 0; l < 32; l++) {
                const float p = ss[u][l];
                a0 = fmaf(p, vs[l][2 * lane],     a0);
                a1 = fmaf(p, vs[l][2 * lane + 1], a1);
            }
            accs[u][2 * lane]     = a0;
            accs[u][2 * lane + 1] = a1;
        }
    }
    __syncthreads();

    for (int i = t; i < U_ * D_; i += 256) {
        int u = i >> 6, d = i & 63;
        g_ctx[((size_t)bh * L_ + mt[u]) * D_ + d] = accs[u][d] / srow[u];
    }
}

// ---------------------------------------------------------------------------
// Kernel 6: out = ctx(32768x512) @ Wo(512x64).  64x64 tile, BK=32, 4x4 micro.
// ---------------------------------------------------------------------------
__global__ __launch_bounds__(256) void out_gemm(const float* __restrict__ Wo,
                                                float* __restrict__ out)
{
    __shared__ float As[32][64];
    __shared__ float Bs[32][64];

    const int t  = threadIdx.x;
    const int tx = t & 15;
    const int ty = t >> 4;
    const size_t m0 = (size_t)blockIdx.x * 64;

    float acc[4][4];
#pragma unroll
    for (int i = 0; i < 4; i++)
#pragma unroll
        for (int j = 0; j < 4; j++) acc[i][j] = 0.f;

    for (int kb = 0; kb < HID_; kb += 32) {
        __syncthreads();
#pragma unroll
        for (int i = 0; i < 2; i++) {
            int f    = t + 256 * i;
            int arow = f >> 3;
            int ac4  = (f & 7) * 4;
            float4 av = *(const float4*)(g_ctx + (m0 + arow) * HID_ + kb + ac4);
            As[ac4 + 0][arow] = av.x;
            As[ac4 + 1][arow] = av.y;
            As[ac4 + 2][arow] = av.z;
            As[ac4 + 3][arow] = av.w;
            int brow = f >> 4;
            int bc4  = (f & 15) * 4;
            *(float4*)&Bs[brow][bc4] = *(const float4*)(Wo + (size_t)(kb + brow) * 64 + bc4);
        }
        __syncthreads();
#pragma unroll
        for (int k = 0; k < 32; k++) {
            float a[4], b[4];
            *(float4*)a = *(const float4*)&As[k][ty * 4];
            *(float4*)b = *(const float4*)&Bs[k][tx * 4];
#pragma unroll
            for (int i = 0; i < 4; i++)
#pragma unroll
                for (int j = 0; j < 4; j++)
                    acc[i][j] = fmaf(a[i], b[j], acc[i][j]);
        }
    }

#pragma unroll
    for (int i = 0; i < 4; i++) {
        float4 o = make_float4(acc[i][0], acc[i][1], acc[i][2], acc[i][3]);
        *(float4*)(out + (m0 + ty * 4 + i) * 64 + tx * 4) = o;
    }
}

// ---------------------------------------------------------------------------
extern "C" void kernel_launch(void* const* d_in, const int* in_sizes, int n_in,
                              void* d_out, int out_size)
{
    (void)in_sizes; (void)n_in; (void)out_size;
    const float* q_in = (const float*)d_in[0];
    const float* k_in = (const float*)d_in[1];
    const float* v_in = (const float*)d_in[2];
    const float* Wq   = (const float*)d_in[3];
    const float* Wk   = (const float*)d_in[4];
    const float* Wv   = (const float*)d_in[5];
    const float* Wo   = (const float*)d_in[6];
    const int*   idx  = (const int*)d_in[7];
    float* out = (float*)d_out;

    split_in<<<dim3(MROWS * DIN_ / (4 * 256), 3), 256>>>(q_in, k_in, v_in);
    split_w<<<dim3(DIN_ * HID_ / 256, 3), 256>>>(Wq, Wk, Wv);
    gemm_qkv_mma<<<dim3(HID_ / 128, MROWS / 128, 3), 256>>>();
    dot_kernel<<<(BH_ * L_) / 8, 256>>>(idx);
    topk_kernel<<<BH_, 256>>>();
    cumsum_kernel<<<BH_, 1024>>>();
    attn_kernel<<<BH_, 256>>>();
    out_gemm<<<MROWS / 64, 256>>>(Wo, out);
}